// round 1
// baseline (speedup 1.0000x reference)
#include <cuda_runtime.h>
#include <math.h>

#define N_RAYS   4096
#define PSTEPS   254
#define P_INNER  231
#define MTOT     (N_RAYS*PSTEPS)      // 1,040,384
#define WORLD    160
#define S2       (WORLD*WORLD)        // 25600
#define S3       (WORLD*WORLD*WORLD)  // 4,096,000
#define K0DIM    12
#define WIDTH    128
#define DIM0     39
#define ACT_SHIFT (-9.210240371976183f)
#define BG_LEN   0.2f

// ---------------- scratch (device globals: allowed; no runtime alloc) ----------------
__device__ float g_k0T[K0DIM * MTOT];   // transposed k0 features [c][s]  (~50 MB)
__device__ float g_alpha[MTOT];
__device__ float g_w[MTOT];
__device__ float g_vemb[N_RAYS * 27];

// ---------------- K1: sampling + contraction + trilinear interp ----------------
__global__ void k_sample(const float* __restrict__ ro, const float* __restrict__ rdir,
                         const float* __restrict__ dgrid, const float* __restrict__ k0g,
                         const int* __restrict__ stepsize)
{
    int s = blockIdx.x * blockDim.x + threadIdx.x;
    if (s >= MTOT) return;
    int r = s / PSTEPS;
    int p = s - r * PSTEPS;

    const float SQ3x2 = 3.4641016151377546f;  // 2*sqrt(3)
    float t;
    if (p < P_INNER) {
        t = SQ3x2 * ((float)p + 0.5f) * (1.0f / 231.0f);
    } else {
        int q = p - P_INNER;                  // 0..22
        float L0 = 1.0f - (float)q     * (0.999f / 23.0f);
        float L1 = 1.0f - (float)(q+1) * (0.999f / 23.0f);
        t = 0.5f * SQ3x2 * (1.0f / L0 + 1.0f / L1);
    }

    float dx = rdir[r*3+0], dy = rdir[r*3+1], dz = rdir[r*3+2];
    float inv = rsqrtf(dx*dx + dy*dy + dz*dz);
    dx *= inv; dy *= inv; dz *= inv;

    float px = ro[r*3+0] + dx * t;
    float py = ro[r*3+1] + dy * t;
    float pz = ro[r*3+2] + dz * t;

    float nm = fmaxf(fabsf(px), fmaxf(fabsf(py), fabsf(pz)));
    if (nm > 1.0f) {
        float sc = (1.0f + BG_LEN - BG_LEN / nm) / nm;
        px *= sc; py *= sc; pz *= sc;
    }

    const float GS = 159.0f / 2.4f;
    float gx = fminf(fmaxf((px + 1.2f) * GS, 0.0f), 159.0f);
    float gy = fminf(fmaxf((py + 1.2f) * GS, 0.0f), 159.0f);
    float gz = fminf(fmaxf((pz + 1.2f) * GS, 0.0f), 159.0f);
    int ix = min((int)gx, 158);
    int iy = min((int)gy, 158);
    int iz = min((int)gz, 158);
    float fx = gx - (float)ix, fy = gy - (float)iy, fz = gz - (float)iz;

    int base = (ix * WORLD + iy) * WORLD + iz;
    float w00 = (1.f-fx)*(1.f-fy), w01 = (1.f-fx)*fy, w10 = fx*(1.f-fy), w11 = fx*fy;
    float wz0 = 1.f - fz, wz1 = fz;

    float wt[8];
    wt[0]=w00*wz0; wt[1]=w00*wz1; wt[2]=w01*wz0; wt[3]=w01*wz1;
    wt[4]=w10*wz0; wt[5]=w10*wz1; wt[6]=w11*wz0; wt[7]=w11*wz1;
    int off[8];
    off[0]=base;        off[1]=base+1;
    off[2]=base+WORLD;  off[3]=base+WORLD+1;
    off[4]=base+S2;     off[5]=base+S2+1;
    off[6]=base+S2+WORLD; off[7]=base+S2+WORLD+1;

    // density -> alpha
    float dsum = 0.0f;
    #pragma unroll
    for (int u = 0; u < 8; u++) dsum += wt[u] * __ldg(&dgrid[off[u]]);

    // stepsize may arrive as int32 or float32 bits — handle both deterministically
    int sv = *stepsize;
    float interval = (sv > 0 && sv < 1000000) ? (float)sv : __int_as_float(sv);

    float x = dsum + ACT_SHIFT;
    float sp = (x > 20.0f) ? x : log1pf(expf(x));           // softplus
    g_alpha[s] = 1.0f - expf(-interval * sp);

    // k0 channels (transposed store -> coalesced reads in MLP)
    #pragma unroll
    for (int c = 0; c < K0DIM; c++) {
        const float* gp = k0g + c * S3;
        float v = 0.0f;
        #pragma unroll
        for (int u = 0; u < 8; u++) v += wt[u] * __ldg(&gp[off[u]]);
        g_k0T[c * MTOT + s] = v;
    }
}

// ---------------- K2: per-ray view embedding + transmittance scan + out init ----------------
__global__ void k_scan(const float* __restrict__ vdirs, float* __restrict__ out)
{
    int r = blockIdx.x * blockDim.x + threadIdx.x;
    if (r >= N_RAYS) return;

    float d[3];
    d[0] = vdirs[r*3+0]; d[1] = vdirs[r*3+1]; d[2] = vdirs[r*3+2];
    float* ve = &g_vemb[r * 27];
    ve[0] = d[0]; ve[1] = d[1]; ve[2] = d[2];
    #pragma unroll
    for (int c = 0; c < 3; c++) {
        #pragma unroll
        for (int e = 0; e < 4; e++) {
            float v = d[c] * (float)(1 << e);
            ve[3  + c*4 + e] = sinf(v);
            ve[15 + c*4 + e] = cosf(v);
        }
    }

    float T = 1.0f;
    int base = r * PSTEPS;
    for (int p = 0; p < PSTEPS; p++) {
        float a = g_alpha[base + p];
        g_w[base + p] = a * T;
        T *= (1.0f - a);
    }
    // init output with background term (overwrites 0xAA poison)
    out[r*3+0] = T; out[r*3+1] = T; out[r*3+2] = T;   // BG = 1.0
}

// ---------------- K3: fused MLP (39->128->128->3) + weighted accumulation ----------------
#define TILE     256
#define HSTRIDE  132   // pad 128 -> 132 (16B-aligned stride, conflict-free float4 access)

#define OFF_W0   0
#define OFF_B0   4992
#define OFF_W1   5120
#define OFF_B1   21504
#define OFF_W2   21632
#define OFF_H    22016
#define SMEM_FLOATS (OFF_H + TILE*HSTRIDE)   // 55808 floats = 223,232 B

__global__ void __launch_bounds__(256, 1) k_mlp(
    const float* __restrict__ w0, const float* __restrict__ b0,
    const float* __restrict__ w1, const float* __restrict__ b1,
    const float* __restrict__ w2, const float* __restrict__ b2,
    float* __restrict__ out)
{
    extern __shared__ float sm[];
    int tid = threadIdx.x;

    for (int i = tid; i < 4992;  i += 256) sm[OFF_W0 + i] = w0[i];
    for (int i = tid; i < 128;   i += 256) sm[OFF_B0 + i] = b0[i];
    for (int i = tid; i < 16384; i += 256) sm[OFF_W1 + i] = w1[i];
    for (int i = tid; i < 128;   i += 256) sm[OFF_B1 + i] = b1[i];
    for (int i = tid; i < 384;   i += 256) sm[OFF_W2 + i] = w2[i];

    int s = blockIdx.x * TILE + tid;       // MTOT % 256 == 0
    int r = s / PSTEPS;

    // feature vector fully in registers: k0 (12) + view embedding (27)
    float ft[DIM0];
    #pragma unroll
    for (int c = 0; c < 12; c++) ft[c] = g_k0T[c * MTOT + s];
    #pragma unroll
    for (int k = 0; k < 27; k++) ft[12 + k] = g_vemb[r * 27 + k];

    __syncthreads();

    float* myH = &sm[OFF_H + tid * HSTRIDE];
    const float* sW0 = &sm[OFF_W0];
    const float* sW1 = &sm[OFF_W1];
    const float* sW2 = &sm[OFF_W2];

    // ---- layer 0: 39 -> 128 (relu) ----
    #pragma unroll 1
    for (int jc = 0; jc < 16; jc++) {
        float acc[8];
        #pragma unroll
        for (int j = 0; j < 8; j++) acc[j] = sm[OFF_B0 + jc*8 + j];
        #pragma unroll
        for (int k = 0; k < DIM0; k++) {
            float f = ft[k];
            float4 wa = *(const float4*)&sW0[k*128 + jc*8];
            float4 wb = *(const float4*)&sW0[k*128 + jc*8 + 4];
            acc[0] = fmaf(f, wa.x, acc[0]); acc[1] = fmaf(f, wa.y, acc[1]);
            acc[2] = fmaf(f, wa.z, acc[2]); acc[3] = fmaf(f, wa.w, acc[3]);
            acc[4] = fmaf(f, wb.x, acc[4]); acc[5] = fmaf(f, wb.y, acc[5]);
            acc[6] = fmaf(f, wb.z, acc[6]); acc[7] = fmaf(f, wb.w, acc[7]);
        }
        #pragma unroll
        for (int j = 0; j < 8; j++) myH[jc*8 + j] = fmaxf(acc[j], 0.0f);
    }

    // ---- layer 1 (128 -> 128, relu) fused with layer 2 (128 -> 3) ----
    float rgb0 = __ldg(&b2[0]), rgb1 = __ldg(&b2[1]), rgb2 = __ldg(&b2[2]);
    #pragma unroll 1
    for (int jc = 0; jc < 16; jc++) {
        float acc[8];
        #pragma unroll
        for (int j = 0; j < 8; j++) acc[j] = sm[OFF_B1 + jc*8 + j];
        #pragma unroll 8
        for (int k4 = 0; k4 < 32; k4++) {
            float4 h4 = *(const float4*)&myH[k4*4];
            float hh[4] = {h4.x, h4.y, h4.z, h4.w};
            #pragma unroll
            for (int u = 0; u < 4; u++) {
                float h = hh[u];
                float4 wa = *(const float4*)&sW1[(k4*4+u)*128 + jc*8];
                float4 wb = *(const float4*)&sW1[(k4*4+u)*128 + jc*8 + 4];
                acc[0] = fmaf(h, wa.x, acc[0]); acc[1] = fmaf(h, wa.y, acc[1]);
                acc[2] = fmaf(h, wa.z, acc[2]); acc[3] = fmaf(h, wa.w, acc[3]);
                acc[4] = fmaf(h, wb.x, acc[4]); acc[5] = fmaf(h, wb.y, acc[5]);
                acc[6] = fmaf(h, wb.z, acc[6]); acc[7] = fmaf(h, wb.w, acc[7]);
            }
        }
        #pragma unroll
        for (int j = 0; j < 8; j++) {
            float hv = fmaxf(acc[j], 0.0f);
            int jj = jc*8 + j;
            rgb0 = fmaf(hv, sW2[jj*3+0], rgb0);
            rgb1 = fmaf(hv, sW2[jj*3+1], rgb1);
            rgb2 = fmaf(hv, sW2[jj*3+2], rgb2);
        }
    }

    float wgt = g_w[s];
    rgb0 = wgt / (1.0f + expf(-rgb0));   // weight * sigmoid
    rgb1 = wgt / (1.0f + expf(-rgb1));
    rgb2 = wgt / (1.0f + expf(-rgb2));

    atomicAdd(&out[r*3+0], rgb0);
    atomicAdd(&out[r*3+1], rgb1);
    atomicAdd(&out[r*3+2], rgb2);
}

// ---------------- launcher ----------------
extern "C" void kernel_launch(void* const* d_in, const int* in_sizes, int n_in,
                              void* d_out, int out_size)
{
    const float* rays_o   = (const float*)d_in[0];
    const float* rays_d   = (const float*)d_in[1];
    const float* viewdirs = (const float*)d_in[2];
    const float* dgrid    = (const float*)d_in[3];
    const float* k0g      = (const float*)d_in[4];
    const float* w0 = (const float*)d_in[5];
    const float* b0 = (const float*)d_in[6];
    const float* w1 = (const float*)d_in[7];
    const float* b1 = (const float*)d_in[8];
    const float* w2 = (const float*)d_in[9];
    const float* b2 = (const float*)d_in[10];
    const int* stepsize = (const int*)d_in[11];
    float* out = (float*)d_out;

    static_assert(SMEM_FLOATS * 4 <= 232448, "smem too big");
    cudaFuncSetAttribute(k_mlp, cudaFuncAttributeMaxDynamicSharedMemorySize, SMEM_FLOATS * 4);

    k_sample<<<(MTOT + 255) / 256, 256>>>(rays_o, rays_d, dgrid, k0g, stepsize);
    k_scan<<<(N_RAYS + 255) / 256, 256>>>(viewdirs, out);
    k_mlp<<<MTOT / TILE, 256, SMEM_FLOATS * 4>>>(w0, b0, w1, b1, w2, b2, out);
}

// round 3
// speedup vs baseline: 4.7998x; 4.7998x over previous
#include <cuda_runtime.h>
#include <cuda_bf16.h>
#include <math.h>
#include <stdint.h>

#define N_RAYS   4096
#define PSTEPS   254
#define P_INNER  231
#define MTOT     (N_RAYS*PSTEPS)      // 1,040,384
#define NTILES   (MTOT/128)           // 8128
#define WORLD    160
#define S2       (WORLD*WORLD)
#define S3       (WORLD*WORLD*WORLD)
#define ACT_SHIFT (-9.210240371976183f)
#define BG_LEN   0.2f
#define GRID_MLP 148

// ---------------- scratch ----------------
__device__ uint16_t g_fhi[MTOT*16];     // k0 features bf16-hi rows (12 real + 4 pad)
__device__ uint16_t g_flo[MTOT*16];     // residual (lo) rows
__device__ float    g_vembf[N_RAYS*27]; // view embedding fp32
__device__ float    g_h0v[N_RAYS*128];  // per-ray layer0 contribution of vemb + b0
__device__ float    g_alpha[MTOT];
__device__ float    g_w[MTOT];

// ---------------- helpers ----------------
__device__ __forceinline__ uint16_t f2bf(float f) {
    return __bfloat16_as_ushort(__float2bfloat16(f));
}
__device__ __forceinline__ float bf2f(uint16_t u) {
    return __bfloat162float(__ushort_as_bfloat16(u));
}
__device__ __forceinline__ uint32_t pack_bf2(float f0, float f1) {   // f0 -> low half
    __nv_bfloat162 v = __floats2bfloat162_rn(f0, f1);
    return *reinterpret_cast<uint32_t*>(&v);
}
__device__ __forceinline__ uint32_t smem_u32(const void* p) {
    uint32_t a;
    asm("{ .reg .u64 t; cvta.to.shared.u64 t, %1; cvt.u32.u64 %0, t; }" : "=r"(a) : "l"(p));
    return a;
}

#define LDSM_X4(r0,r1,r2,r3,addr) \
    asm volatile("ldmatrix.sync.aligned.m8n8.x4.shared.b16 {%0,%1,%2,%3}, [%4];" \
        : "=r"(r0), "=r"(r1), "=r"(r2), "=r"(r3) : "r"(addr))

#define MMA_BF16(c, a0,a1,a2,a3, b0,b1) \
    asm volatile("mma.sync.aligned.m16n8k16.row.col.f32.bf16.bf16.f32 " \
        "{%0,%1,%2,%3}, {%4,%5,%6,%7}, {%8,%9}, {%0,%1,%2,%3};" \
        : "+f"((c)[0]), "+f"((c)[1]), "+f"((c)[2]), "+f"((c)[3]) \
        : "r"(a0), "r"(a1), "r"(a2), "r"(a3), "r"(b0), "r"(b1))

// ---------------- K1: sampling + contraction + trilinear interp ----------------
__global__ void k_sample(const float* __restrict__ ro, const float* __restrict__ rdir,
                         const float* __restrict__ dgrid, const float* __restrict__ k0g,
                         const int* __restrict__ stepsize)
{
    int s = blockIdx.x * blockDim.x + threadIdx.x;
    if (s >= MTOT) return;
    int r = s / PSTEPS;
    int p = s - r * PSTEPS;

    const float SQ3x2 = 3.4641016151377546f;
    float t;
    if (p < P_INNER) {
        t = SQ3x2 * ((float)p + 0.5f) * (1.0f / 231.0f);
    } else {
        int q = p - P_INNER;
        float L0 = 1.0f - (float)q     * (0.999f / 23.0f);
        float L1 = 1.0f - (float)(q+1) * (0.999f / 23.0f);
        t = 0.5f * SQ3x2 * (1.0f / L0 + 1.0f / L1);
    }

    float dx = rdir[r*3+0], dy = rdir[r*3+1], dz = rdir[r*3+2];
    float inv = rsqrtf(dx*dx + dy*dy + dz*dz);
    dx *= inv; dy *= inv; dz *= inv;

    float px = ro[r*3+0] + dx * t;
    float py = ro[r*3+1] + dy * t;
    float pz = ro[r*3+2] + dz * t;

    float nm = fmaxf(fabsf(px), fmaxf(fabsf(py), fabsf(pz)));
    if (nm > 1.0f) {
        float sc = (1.0f + BG_LEN - BG_LEN / nm) / nm;
        px *= sc; py *= sc; pz *= sc;
    }

    const float GS = 159.0f / 2.4f;
    float gx = fminf(fmaxf((px + 1.2f) * GS, 0.0f), 159.0f);
    float gy = fminf(fmaxf((py + 1.2f) * GS, 0.0f), 159.0f);
    float gz = fminf(fmaxf((pz + 1.2f) * GS, 0.0f), 159.0f);
    int ix = min((int)gx, 158);
    int iy = min((int)gy, 158);
    int iz = min((int)gz, 158);
    float fx = gx - (float)ix, fy = gy - (float)iy, fz = gz - (float)iz;

    int base = (ix * WORLD + iy) * WORLD + iz;
    float w00 = (1.f-fx)*(1.f-fy), w01 = (1.f-fx)*fy, w10 = fx*(1.f-fy), w11 = fx*fy;
    float wz0 = 1.f - fz, wz1 = fz;

    float wt[8];
    wt[0]=w00*wz0; wt[1]=w00*wz1; wt[2]=w01*wz0; wt[3]=w01*wz1;
    wt[4]=w10*wz0; wt[5]=w10*wz1; wt[6]=w11*wz0; wt[7]=w11*wz1;
    int off[8];
    off[0]=base;          off[1]=base+1;
    off[2]=base+WORLD;    off[3]=base+WORLD+1;
    off[4]=base+S2;       off[5]=base+S2+1;
    off[6]=base+S2+WORLD; off[7]=base+S2+WORLD+1;

    float dsum = 0.0f;
    #pragma unroll
    for (int u = 0; u < 8; u++) dsum += wt[u] * __ldg(&dgrid[off[u]]);

    int sv = *stepsize;
    float interval = (sv > 0 && sv < 1000000) ? (float)sv : __int_as_float(sv);

    float x = dsum + ACT_SHIFT;
    float sp = (x > 20.0f) ? x : log1pf(expf(x));
    g_alpha[s] = 1.0f - expf(-interval * sp);

    // k0 channels -> bf16 hi/lo packed rows (12 values + 4 zero pad)
    float v[12];
    #pragma unroll
    for (int c = 0; c < 12; c++) {
        const float* gp = k0g + c * S3;
        float acc = 0.0f;
        #pragma unroll
        for (int u = 0; u < 8; u++) acc += wt[u] * __ldg(&gp[off[u]]);
        v[c] = acc;
    }
    uint32_t phi[8], plo[8];
    #pragma unroll
    for (int c = 0; c < 6; c++) {
        float a = v[2*c], b = v[2*c+1];
        uint32_t h = pack_bf2(a, b);
        phi[c] = h;
        float ha = __uint_as_float(h << 16);
        float hb = __uint_as_float(h & 0xffff0000u);
        plo[c] = pack_bf2(a - ha, b - hb);
    }
    phi[6]=phi[7]=plo[6]=plo[7]=0u;
    uint4* dh = (uint4*)&g_fhi[(size_t)s*16];
    uint4* dl = (uint4*)&g_flo[(size_t)s*16];
    dh[0] = make_uint4(phi[0],phi[1],phi[2],phi[3]);
    dh[1] = make_uint4(phi[4],phi[5],phi[6],phi[7]);
    dl[0] = make_uint4(plo[0],plo[1],plo[2],plo[3]);
    dl[1] = make_uint4(plo[4],plo[5],plo[6],plo[7]);
}

// ---------------- K2: view embedding + transmittance scan + out init ----------------
__global__ void k_scan(const float* __restrict__ vdirs, float* __restrict__ out)
{
    int r = blockIdx.x * blockDim.x + threadIdx.x;
    if (r >= N_RAYS) return;

    float d[3];
    d[0] = vdirs[r*3+0]; d[1] = vdirs[r*3+1]; d[2] = vdirs[r*3+2];
    float* ve = &g_vembf[r * 27];
    ve[0] = d[0]; ve[1] = d[1]; ve[2] = d[2];
    #pragma unroll
    for (int c = 0; c < 3; c++)
        #pragma unroll
        for (int e = 0; e < 4; e++) {
            float vv = d[c] * (float)(1 << e);
            ve[3  + c*4 + e] = sinf(vv);
            ve[15 + c*4 + e] = cosf(vv);
        }

    float T = 1.0f;
    int base = r * PSTEPS;
    for (int p = 0; p < PSTEPS; p++) {
        float a = g_alpha[base + p];
        g_w[base + p] = a * T;
        T *= (1.0f - a);
    }
    out[r*3+0] = T; out[r*3+1] = T; out[r*3+2] = T;   // BG = 1.0
}

// ---------------- K2b: per-ray layer0 view contribution: h0v = b0 + vemb @ W0[12:39] ----------------
__global__ void k_h0v(const float* __restrict__ w0, const float* __restrict__ b0)
{
    int gid = blockIdx.x * blockDim.x + threadIdx.x;   // 4096*128 threads
    int r = gid >> 7, n = gid & 127;
    float acc = __ldg(&b0[n]);
    #pragma unroll
    for (int k = 0; k < 27; k++)
        acc = fmaf(g_vembf[r*27 + k], __ldg(&w0[(12+k)*128 + n]), acc);
    g_h0v[r*128 + n] = acc;
}

// ---------------- K3: persistent mma.sync MLP ----------------
// smem layout (bytes)
#define SM_B1V   0                     // 128 floats
#define SM_W2    512                   // 384 floats
#define SM_A0H   2048                  // [128 rows][24 bf16] stride 48B
#define SM_A0L   8192
#define SM_B0H   14336                 // [128 n][24 k] stride 48B (k 0..15 real)
#define SM_B0L   20480
#define SM_B1H   26624                 // [128 n][136 k] stride 272B (k 0..127 real)
#define SM_B1L   61440
#define SMEM_TOTAL 96256

__global__ void __launch_bounds__(256, 1) k_mlp(
    const float* __restrict__ w0, const float* __restrict__ b0,
    const float* __restrict__ w1, const float* __restrict__ b1,
    const float* __restrict__ w2, const float* __restrict__ b2,
    float* __restrict__ out)
{
    extern __shared__ unsigned char smem[];
    uint32_t sb = smem_u32(smem);
    int tid = threadIdx.x;
    int w = tid >> 5, l = tid & 31;
    int g = l >> 2, tg = l & 3;

    // ---- one-time weight staging (bf16 hi/lo, [n][k] layout) ----
    if (tid < 128) ((float*)(smem + SM_B1V))[tid] = b1[tid];
    for (int i = tid; i < 384; i += 256) ((float*)(smem + SM_W2))[i] = w2[i];

    for (int idx = tid; idx < 128*16; idx += 256) {
        int n = idx & 127, k = idx >> 7;
        float v = (k < 12) ? w0[k*128 + n] : 0.0f;
        uint16_t h = f2bf(v);
        uint16_t lo16 = f2bf(v - bf2f(h));
        *(uint16_t*)(smem + SM_B0H + n*48 + k*2) = h;
        *(uint16_t*)(smem + SM_B0L + n*48 + k*2) = lo16;
    }
    for (int idx = tid; idx < 128*128; idx += 256) {
        int n = idx & 127, k = idx >> 7;
        float v = w1[k*128 + n];
        uint16_t h = f2bf(v);
        uint16_t lo16 = f2bf(v - bf2f(h));
        *(uint16_t*)(smem + SM_B1H + n*272 + k*2) = h;
        *(uint16_t*)(smem + SM_B1L + n*272 + k*2) = lo16;
    }
    float b2r0 = __ldg(&b2[0]), b2r1 = __ldg(&b2[1]), b2r2 = __ldg(&b2[2]);
    const float* b1s = (const float*)(smem + SM_B1V);
    const float* w2s = (const float*)(smem + SM_W2);
    __syncthreads();

    // ---- lane-invariant ldmatrix addresses ----
    uint32_t rowA = 16u*w + (l & 7) + ((l >> 3) & 1) * 8;
    uint32_t colA = (uint32_t)(l >> 4) * 16;
    uint32_t aA0H = sb + SM_A0H + rowA*48 + colA;
    uint32_t aA0L = sb + SM_A0L + rowA*48 + colA;
    uint32_t lrow = (l & 7) + ((l >> 4) & 1) * 8;    // row within 16-row pair block
    uint32_t lcol = ((l >> 3) & 1) * 16;             // 8-element k offset in bytes
    uint32_t aB0H = sb + SM_B0H + lrow*48  + lcol;
    uint32_t aB0L = sb + SM_B0L + lrow*48  + lcol;
    uint32_t aB1H = sb + SM_B1H + lrow*272 + lcol;
    uint32_t aB1L = sb + SM_B1L + lrow*272 + lcol;

    for (int m = blockIdx.x; m < NTILES; m += gridDim.x) {
        int mbase = m * 128;

        // ---- stage A0: threads <128 hi rows, >=128 lo rows ----
        {
            int srow = tid & 127;
            const uint16_t* src = (tid < 128) ? &g_fhi[(size_t)(mbase+srow)*16]
                                              : &g_flo[(size_t)(mbase+srow)*16];
            uint4 q0 = ((const uint4*)src)[0];
            uint4 q1 = ((const uint4*)src)[1];
            uint32_t ab = (tid < 128) ? (uint32_t)SM_A0H : (uint32_t)SM_A0L;
            *(uint4*)(smem + ab + srow*48)      = q0;
            *(uint4*)(smem + ab + srow*48 + 16) = q1;
        }
        __syncthreads();

        // ---- layer 0: C0[16x128] = A0[16x16] * B0[16x128], 3-pass hi/lo ----
        float c[16][4];
        #pragma unroll
        for (int i = 0; i < 16; i++) { c[i][0]=c[i][1]=c[i][2]=c[i][3]=0.f; }

        uint32_t aH00,aH01,aH02,aH03, aL00,aL01,aL02,aL03;
        LDSM_X4(aH00,aH01,aH02,aH03, aA0H);
        LDSM_X4(aL00,aL01,aL02,aL03, aA0L);
        #pragma unroll
        for (int p = 0; p < 8; p++) {
            uint32_t bh0,bh1,bh2,bh3, bl0,bl1,bl2,bl3;
            LDSM_X4(bh0,bh1,bh2,bh3, aB0H + p*768);
            LDSM_X4(bl0,bl1,bl2,bl3, aB0L + p*768);
            MMA_BF16(c[2*p],   aH00,aH01,aH02,aH03, bh0,bh1);
            MMA_BF16(c[2*p],   aH00,aH01,aH02,aH03, bl0,bl1);
            MMA_BF16(c[2*p],   aL00,aL01,aL02,aL03, bh0,bh1);
            MMA_BF16(c[2*p+1], aH00,aH01,aH02,aH03, bh2,bh3);
            MMA_BF16(c[2*p+1], aH00,aH01,aH02,aH03, bl2,bl3);
            MMA_BF16(c[2*p+1], aL00,aL01,aL02,aL03, bh2,bh3);
        }

        // ---- epilogue 0: + per-ray h0v, relu, bf16 hi/lo split -> A1 frags in registers ----
        int s0 = mbase + 16*w + g;
        int s1 = s0 + 8;
        int r0 = s0 / PSTEPS, r1 = s1 / PSTEPS;
        const float* h0p = g_h0v + (size_t)r0*128;
        const float* h1p = g_h0v + (size_t)r1*128;

        uint32_t aH1[8][4], aL1[8][4];
        #pragma unroll
        for (int ks = 0; ks < 8; ks++) {
            #pragma unroll
            for (int hh = 0; hh < 2; hh++) {
                int nt = 2*ks + hh;
                int col = nt*8 + tg*2;
                float f00 = fmaxf(c[nt][0] + h0p[col],   0.f);
                float f01 = fmaxf(c[nt][1] + h0p[col+1], 0.f);
                float f10 = fmaxf(c[nt][2] + h1p[col],   0.f);
                float f11 = fmaxf(c[nt][3] + h1p[col+1], 0.f);
                uint32_t p0 = pack_bf2(f00, f01);
                uint32_t p1 = pack_bf2(f10, f11);
                aH1[ks][0+hh*2] = p0;
                aH1[ks][1+hh*2] = p1;
                aL1[ks][0+hh*2] = pack_bf2(f00 - __uint_as_float(p0 << 16),
                                           f01 - __uint_as_float(p0 & 0xffff0000u));
                aL1[ks][1+hh*2] = pack_bf2(f10 - __uint_as_float(p1 << 16),
                                           f11 - __uint_as_float(p1 & 0xffff0000u));
            }
        }

        // ---- layer 1: C1[16x128] = A1[16x128] * B1[128x128], 3-pass hi/lo ----
        #pragma unroll
        for (int i = 0; i < 16; i++) { c[i][0]=c[i][1]=c[i][2]=c[i][3]=0.f; }
        #pragma unroll
        for (int ks = 0; ks < 8; ks++) {
            #pragma unroll
            for (int p = 0; p < 8; p++) {
                uint32_t bh0,bh1,bh2,bh3, bl0,bl1,bl2,bl3;
                LDSM_X4(bh0,bh1,bh2,bh3, aB1H + p*4352 + ks*32);
                LDSM_X4(bl0,bl1,bl2,bl3, aB1L + p*4352 + ks*32);
                MMA_BF16(c[2*p],   aH1[ks][0],aH1[ks][1],aH1[ks][2],aH1[ks][3], bh0,bh1);
                MMA_BF16(c[2*p],   aH1[ks][0],aH1[ks][1],aH1[ks][2],aH1[ks][3], bl0,bl1);
                MMA_BF16(c[2*p],   aL1[ks][0],aL1[ks][1],aL1[ks][2],aL1[ks][3], bh0,bh1);
                MMA_BF16(c[2*p+1], aH1[ks][0],aH1[ks][1],aH1[ks][2],aH1[ks][3], bh2,bh3);
                MMA_BF16(c[2*p+1], aH1[ks][0],aH1[ks][1],aH1[ks][2],aH1[ks][3], bl2,bl3);
                MMA_BF16(c[2*p+1], aL1[ks][0],aL1[ks][1],aL1[ks][2],aL1[ks][3], bh2,bh3);
            }
        }

        // ---- epilogue 1: relu, layer2 (128->3), quad reduce, sigmoid, weighted atomic ----
        float p00=0.f,p01=0.f,p02=0.f, p10=0.f,p11=0.f,p12=0.f;
        #pragma unroll
        for (int nt = 0; nt < 16; nt++) {
            int col = nt*8 + tg*2;
            float f0 = fmaxf(c[nt][0] + b1s[col],   0.f);
            float f1 = fmaxf(c[nt][1] + b1s[col+1], 0.f);
            float f2 = fmaxf(c[nt][2] + b1s[col],   0.f);
            float f3 = fmaxf(c[nt][3] + b1s[col+1], 0.f);
            float wa0 = w2s[col*3+0],     wa1 = w2s[col*3+1],     wa2 = w2s[col*3+2];
            float wb0 = w2s[(col+1)*3+0], wb1 = w2s[(col+1)*3+1], wb2 = w2s[(col+1)*3+2];
            p00 = fmaf(f0, wa0, fmaf(f1, wb0, p00));
            p01 = fmaf(f0, wa1, fmaf(f1, wb1, p01));
            p02 = fmaf(f0, wa2, fmaf(f1, wb2, p02));
            p10 = fmaf(f2, wa0, fmaf(f3, wb0, p10));
            p11 = fmaf(f2, wa1, fmaf(f3, wb1, p11));
            p12 = fmaf(f2, wa2, fmaf(f3, wb2, p12));
        }
        #pragma unroll
        for (int d = 1; d <= 2; d <<= 1) {
            p00 += __shfl_xor_sync(0xffffffffu, p00, d);
            p01 += __shfl_xor_sync(0xffffffffu, p01, d);
            p02 += __shfl_xor_sync(0xffffffffu, p02, d);
            p10 += __shfl_xor_sync(0xffffffffu, p10, d);
            p11 += __shfl_xor_sync(0xffffffffu, p11, d);
            p12 += __shfl_xor_sync(0xffffffffu, p12, d);
        }
        if (tg == 0) {
            float wg0 = g_w[s0], wg1 = g_w[s1];
            float v00 = wg0 / (1.0f + expf(-(p00 + b2r0)));
            float v01 = wg0 / (1.0f + expf(-(p01 + b2r1)));
            float v02 = wg0 / (1.0f + expf(-(p02 + b2r2)));
            float v10 = wg1 / (1.0f + expf(-(p10 + b2r0)));
            float v11 = wg1 / (1.0f + expf(-(p11 + b2r1)));
            float v12 = wg1 / (1.0f + expf(-(p12 + b2r2)));
            atomicAdd(&out[r0*3+0], v00);
            atomicAdd(&out[r0*3+1], v01);
            atomicAdd(&out[r0*3+2], v02);
            atomicAdd(&out[r1*3+0], v10);
            atomicAdd(&out[r1*3+1], v11);
            atomicAdd(&out[r1*3+2], v12);
        }
        __syncthreads();   // protect A0 staging for next tile
    }
}

// ---------------- launcher ----------------
extern "C" void kernel_launch(void* const* d_in, const int* in_sizes, int n_in,
                              void* d_out, int out_size)
{
    const float* rays_o   = (const float*)d_in[0];
    const float* rays_d   = (const float*)d_in[1];
    const float* viewdirs = (const float*)d_in[2];
    const float* dgrid    = (const float*)d_in[3];
    const float* k0g      = (const float*)d_in[4];
    const float* w0 = (const float*)d_in[5];
    const float* b0 = (const float*)d_in[6];
    const float* w1 = (const float*)d_in[7];
    const float* b1 = (const float*)d_in[8];
    const float* w2 = (const float*)d_in[9];
    const float* b2 = (const float*)d_in[10];
    const int* stepsize = (const int*)d_in[11];
    float* out = (float*)d_out;

    cudaFuncSetAttribute(k_mlp, cudaFuncAttributeMaxDynamicSharedMemorySize, SMEM_TOTAL);

    k_sample<<<(MTOT + 255) / 256, 256>>>(rays_o, rays_d, dgrid, k0g, stepsize);
    k_scan<<<(N_RAYS + 255) / 256, 256>>>(viewdirs, out);
    k_h0v<<<(N_RAYS * 128) / 256, 256>>>(w0, b0);
    k_mlp<<<GRID_MLP, 256, SMEM_TOTAL>>>(w0, b0, w1, b1, w2, b2, out);
}

// round 4
// speedup vs baseline: 6.0757x; 1.2658x over previous
#include <cuda_runtime.h>
#include <cuda_bf16.h>
#include <math.h>
#include <stdint.h>

#define N_RAYS   4096
#define PSTEPS   254
#define P_INNER  231
#define MTOT     (N_RAYS*PSTEPS)      // 1,040,384
#define NTILES   (MTOT/128)           // 8128
#define WORLD    160
#define S2       (WORLD*WORLD)
#define S3       (WORLD*WORLD*WORLD)
#define ACT_SHIFT (-9.210240371976183f)
#define BG_LEN   0.2f
#define GRID_MLP 296                  // 2 CTAs per SM

// ---------------- scratch ----------------
__device__ uint16_t g_fhi[MTOT*16];     // k0 features bf16-hi rows (12 real + 4 pad)
__device__ uint16_t g_flo[MTOT*16];     // residual (lo) rows
__device__ float    g_vembf[N_RAYS*27]; // view embedding fp32
__device__ float    g_h0v[N_RAYS*128];  // per-ray layer0 contribution of vemb + b0
__device__ float    g_alpha[MTOT];
__device__ float    g_w[MTOT];

// ---------------- helpers ----------------
__device__ __forceinline__ uint16_t f2bf(float f) {
    return __bfloat16_as_ushort(__float2bfloat16(f));
}
__device__ __forceinline__ float bf2f(uint16_t u) {
    return __bfloat162float(__ushort_as_bfloat16(u));
}
__device__ __forceinline__ uint32_t pack_bf2(float f0, float f1) {   // f0 -> low half
    __nv_bfloat162 v = __floats2bfloat162_rn(f0, f1);
    return *reinterpret_cast<uint32_t*>(&v);
}
__device__ __forceinline__ uint32_t smem_u32(const void* p) {
    uint32_t a;
    asm("{ .reg .u64 t; cvta.to.shared.u64 t, %1; cvt.u32.u64 %0, t; }" : "=r"(a) : "l"(p));
    return a;
}

#define LDSM_X4(r0,r1,r2,r3,addr) \
    asm volatile("ldmatrix.sync.aligned.m8n8.x4.shared.b16 {%0,%1,%2,%3}, [%4];" \
        : "=r"(r0), "=r"(r1), "=r"(r2), "=r"(r3) : "r"(addr))

#define MMA_BF16(c, a0,a1,a2,a3, b0,b1) \
    asm volatile("mma.sync.aligned.m16n8k16.row.col.f32.bf16.bf16.f32 " \
        "{%0,%1,%2,%3}, {%4,%5,%6,%7}, {%8,%9}, {%0,%1,%2,%3};" \
        : "+f"((c)[0]), "+f"((c)[1]), "+f"((c)[2]), "+f"((c)[3]) \
        : "r"(a0), "r"(a1), "r"(a2), "r"(a3), "r"(b0), "r"(b1))

// ---------------- K1: sampling + contraction + trilinear interp ----------------
__global__ void k_sample(const float* __restrict__ ro, const float* __restrict__ rdir,
                         const float* __restrict__ dgrid, const float* __restrict__ k0g,
                         const int* __restrict__ stepsize)
{
    int s = blockIdx.x * blockDim.x + threadIdx.x;
    if (s >= MTOT) return;
    int r = s / PSTEPS;
    int p = s - r * PSTEPS;

    const float SQ3x2 = 3.4641016151377546f;
    float t;
    if (p < P_INNER) {
        t = SQ3x2 * ((float)p + 0.5f) * (1.0f / 231.0f);
    } else {
        int q = p - P_INNER;
        float L0 = 1.0f - (float)q     * (0.999f / 23.0f);
        float L1 = 1.0f - (float)(q+1) * (0.999f / 23.0f);
        t = 0.5f * SQ3x2 * (1.0f / L0 + 1.0f / L1);
    }

    float dx = rdir[r*3+0], dy = rdir[r*3+1], dz = rdir[r*3+2];
    float inv = rsqrtf(dx*dx + dy*dy + dz*dz);
    dx *= inv; dy *= inv; dz *= inv;

    float px = ro[r*3+0] + dx * t;
    float py = ro[r*3+1] + dy * t;
    float pz = ro[r*3+2] + dz * t;

    float nm = fmaxf(fabsf(px), fmaxf(fabsf(py), fabsf(pz)));
    if (nm > 1.0f) {
        float sc = (1.0f + BG_LEN - BG_LEN / nm) / nm;
        px *= sc; py *= sc; pz *= sc;
    }

    const float GS = 159.0f / 2.4f;
    float gx = fminf(fmaxf((px + 1.2f) * GS, 0.0f), 159.0f);
    float gy = fminf(fmaxf((py + 1.2f) * GS, 0.0f), 159.0f);
    float gz = fminf(fmaxf((pz + 1.2f) * GS, 0.0f), 159.0f);
    int ix = min((int)gx, 158);
    int iy = min((int)gy, 158);
    int iz = min((int)gz, 158);
    float fx = gx - (float)ix, fy = gy - (float)iy, fz = gz - (float)iz;

    int base = (ix * WORLD + iy) * WORLD + iz;
    float w00 = (1.f-fx)*(1.f-fy), w01 = (1.f-fx)*fy, w10 = fx*(1.f-fy), w11 = fx*fy;
    float wz0 = 1.f - fz, wz1 = fz;

    float wt[8];
    wt[0]=w00*wz0; wt[1]=w00*wz1; wt[2]=w01*wz0; wt[3]=w01*wz1;
    wt[4]=w10*wz0; wt[5]=w10*wz1; wt[6]=w11*wz0; wt[7]=w11*wz1;
    int off[8];
    off[0]=base;          off[1]=base+1;
    off[2]=base+WORLD;    off[3]=base+WORLD+1;
    off[4]=base+S2;       off[5]=base+S2+1;
    off[6]=base+S2+WORLD; off[7]=base+S2+WORLD+1;

    float dsum = 0.0f;
    #pragma unroll
    for (int u = 0; u < 8; u++) dsum += wt[u] * __ldg(&dgrid[off[u]]);

    int sv = *stepsize;
    float interval = (sv > 0 && sv < 1000000) ? (float)sv : __int_as_float(sv);

    float x = dsum + ACT_SHIFT;
    float sp = (x > 20.0f) ? x : log1pf(expf(x));
    g_alpha[s] = 1.0f - expf(-interval * sp);

    // k0 channels -> bf16 hi/lo packed rows (12 values + 4 zero pad)
    float v[12];
    #pragma unroll
    for (int c = 0; c < 12; c++) {
        const float* gp = k0g + c * S3;
        float acc = 0.0f;
        #pragma unroll
        for (int u = 0; u < 8; u++) acc += wt[u] * __ldg(&gp[off[u]]);
        v[c] = acc;
    }
    uint32_t phi[8], plo[8];
    #pragma unroll
    for (int c = 0; c < 6; c++) {
        float a = v[2*c], b = v[2*c+1];
        uint32_t h = pack_bf2(a, b);
        phi[c] = h;
        float ha = __uint_as_float(h << 16);
        float hb = __uint_as_float(h & 0xffff0000u);
        plo[c] = pack_bf2(a - ha, b - hb);
    }
    phi[6]=phi[7]=plo[6]=plo[7]=0u;
    uint4* dh = (uint4*)&g_fhi[(size_t)s*16];
    uint4* dl = (uint4*)&g_flo[(size_t)s*16];
    dh[0] = make_uint4(phi[0],phi[1],phi[2],phi[3]);
    dh[1] = make_uint4(phi[4],phi[5],phi[6],phi[7]);
    dl[0] = make_uint4(plo[0],plo[1],plo[2],plo[3]);
    dl[1] = make_uint4(plo[4],plo[5],plo[6],plo[7]);
}

// ---------------- K2: warp-parallel view embedding + transmittance scan ----------------
__global__ void k_scan(const float* __restrict__ vdirs, float* __restrict__ out)
{
    int gw = (blockIdx.x * blockDim.x + threadIdx.x) >> 5;   // ray id
    int lane = threadIdx.x & 31;
    if (gw >= N_RAYS) return;

    float d0 = __ldg(&vdirs[gw*3+0]);
    float d1 = __ldg(&vdirs[gw*3+1]);
    float d2 = __ldg(&vdirs[gw*3+2]);

    if (lane < 27) {
        float v;
        if (lane < 3) {
            v = (lane == 0) ? d0 : (lane == 1) ? d1 : d2;
        } else {
            int kk = (lane < 15) ? (lane - 3) : (lane - 15);
            int c = kk >> 2, e = kk & 3;
            float dc = (c == 0) ? d0 : (c == 1) ? d1 : d2;
            float vv = dc * (float)(1 << e);
            v = (lane < 15) ? sinf(vv) : cosf(vv);
        }
        g_vembf[gw*27 + lane] = v;
    }

    float T = 1.0f;
    int base = gw * PSTEPS;
    #pragma unroll
    for (int chunk = 0; chunk < 8; chunk++) {
        int p = chunk*32 + lane;
        float a = (p < PSTEPS) ? g_alpha[base + p] : 0.0f;
        float q = 1.0f - a;
        float incl = q;
        #pragma unroll
        for (int dlt = 1; dlt < 32; dlt <<= 1) {
            float o = __shfl_up_sync(0xffffffffu, incl, dlt);
            if (lane >= dlt) incl *= o;
        }
        float excl = __shfl_up_sync(0xffffffffu, incl, 1);
        if (lane == 0) excl = 1.0f;
        if (p < PSTEPS) g_w[base + p] = a * T * excl;
        float tot = __shfl_sync(0xffffffffu, incl, 31);
        T *= tot;
    }
    if (lane == 0) {
        out[gw*3+0] = T; out[gw*3+1] = T; out[gw*3+2] = T;   // BG = 1.0
    }
}

// ---------------- K2b: per-ray layer0 view contribution: h0v = b0 + vemb @ W0[12:39] ----------------
__global__ void k_h0v(const float* __restrict__ w0, const float* __restrict__ b0)
{
    int gid = blockIdx.x * blockDim.x + threadIdx.x;
    int r = gid >> 7, n = gid & 127;
    float acc = __ldg(&b0[n]);
    #pragma unroll
    for (int k = 0; k < 27; k++)
        acc = fmaf(g_vembf[r*27 + k], __ldg(&w0[(12+k)*128 + n]), acc);
    g_h0v[r*128 + n] = acc;
}

// ---------------- K3: persistent mma.sync MLP, 2 CTAs/SM ----------------
// smem layout (bytes)
#define SM_B1V   0                     // 128 floats
#define SM_W2    512                   // 384 floats
#define SM_A0    2048                  // double buffer: [buf][hi/lo][128 rows][24 bf16] = 2*2*6144
#define SM_B0H   26624                 // [128 n][24 k] stride 48B
#define SM_B0L   32768
#define SM_B1H   38912                 // [128 n][136 k] stride 272B
#define SM_B1L   73728
#define SMEM_TOTAL 108544

__global__ void __launch_bounds__(256, 2) k_mlp(
    const float* __restrict__ w0, const float* __restrict__ b0,
    const float* __restrict__ w1, const float* __restrict__ b1,
    const float* __restrict__ w2, const float* __restrict__ b2,
    float* __restrict__ out)
{
    extern __shared__ unsigned char smem[];
    uint32_t sb = smem_u32(smem);
    int tid = threadIdx.x;
    int w = tid >> 5, l = tid & 31;
    int g = l >> 2, tg = l & 3;

    // ---- one-time weight staging (bf16 hi/lo, [n][k] layout) ----
    if (tid < 128) ((float*)(smem + SM_B1V))[tid] = b1[tid];
    for (int i = tid; i < 384; i += 256) ((float*)(smem + SM_W2))[i] = w2[i];

    for (int idx = tid; idx < 128*16; idx += 256) {
        int n = idx & 127, k = idx >> 7;
        float v = (k < 12) ? w0[k*128 + n] : 0.0f;
        uint16_t h = f2bf(v);
        uint16_t lo16 = f2bf(v - bf2f(h));
        *(uint16_t*)(smem + SM_B0H + n*48 + k*2) = h;
        *(uint16_t*)(smem + SM_B0L + n*48 + k*2) = lo16;
    }
    for (int idx = tid; idx < 128*128; idx += 256) {
        int n = idx & 127, k = idx >> 7;
        float v = w1[k*128 + n];
        uint16_t h = f2bf(v);
        uint16_t lo16 = f2bf(v - bf2f(h));
        *(uint16_t*)(smem + SM_B1H + n*272 + k*2) = h;
        *(uint16_t*)(smem + SM_B1L + n*272 + k*2) = lo16;
    }
    float b2r0 = __ldg(&b2[0]), b2r1 = __ldg(&b2[1]), b2r2 = __ldg(&b2[2]);
    const float* b1s = (const float*)(smem + SM_B1V);
    const float* w2s = (const float*)(smem + SM_W2);

    // ---- lane-invariant ldmatrix addresses ----
    uint32_t rowA = 16u*w + (l & 7) + ((l >> 3) & 1) * 8;
    uint32_t colA = (uint32_t)(l >> 4) * 16;
    uint32_t lrow = (l & 7) + ((l >> 4) & 1) * 8;
    uint32_t lcol = ((l >> 3) & 1) * 16;
    uint32_t aB0H = sb + SM_B0H + lrow*48  + lcol;
    uint32_t aB0L = sb + SM_B0L + lrow*48  + lcol;
    uint32_t aB1H = sb + SM_B1H + lrow*272 + lcol;
    uint32_t aB1L = sb + SM_B1L + lrow*272 + lcol;

    int srow = tid & 127;
    uint32_t halfoff = (tid < 128) ? 0u : 6144u;

    // ---- prime A0 buffer 0 ----
    int m = blockIdx.x;
    if (m < NTILES) {
        const uint16_t* src = (tid < 128) ? &g_fhi[(size_t)(m*128+srow)*16]
                                          : &g_flo[(size_t)(m*128+srow)*16];
        uint4 q0 = ((const uint4*)src)[0];
        uint4 q1 = ((const uint4*)src)[1];
        *(uint4*)(smem + SM_A0 + halfoff + srow*48)      = q0;
        *(uint4*)(smem + SM_A0 + halfoff + srow*48 + 16) = q1;
    }
    __syncthreads();
    int buf = 0;

    for (; m < NTILES; m += gridDim.x) {
        int mbase = m * 128;
        int mn = m + gridDim.x;
        bool hn = mn < NTILES;
        uint4 q0n, q1n;
        if (hn) {   // prefetch next tile rows (hidden under compute)
            const uint16_t* src = (tid < 128) ? &g_fhi[(size_t)(mn*128+srow)*16]
                                              : &g_flo[(size_t)(mn*128+srow)*16];
            q0n = ((const uint4*)src)[0];
            q1n = ((const uint4*)src)[1];
        }

        int s0 = mbase + 16*w + g;
        int s1 = s0 + 8;
        int r0 = s0 / PSTEPS, r1 = s1 / PSTEPS;
        const float* h0p = g_h0v + (size_t)r0*128;
        const float* h1p = g_h0v + (size_t)r1*128;

        // ---- layer 0: K=16, fused epilogue per 16-col chunk -> A1 frags ----
        uint32_t aA0H = sb + SM_A0 + (uint32_t)buf*12288u + rowA*48 + colA;
        uint32_t aA0L = aA0H + 6144;
        uint32_t aH00,aH01,aH02,aH03, aL00,aL01,aL02,aL03;
        LDSM_X4(aH00,aH01,aH02,aH03, aA0H);
        LDSM_X4(aL00,aL01,aL02,aL03, aA0L);

        uint32_t aH1[8][4], aL1[8][4];
        #pragma unroll
        for (int p = 0; p < 8; p++) {
            float cc0[4] = {0.f,0.f,0.f,0.f}, cc1[4] = {0.f,0.f,0.f,0.f};
            uint32_t bh0,bh1,bh2,bh3, bl0,bl1,bl2,bl3;
            LDSM_X4(bh0,bh1,bh2,bh3, aB0H + p*768);
            LDSM_X4(bl0,bl1,bl2,bl3, aB0L + p*768);
            MMA_BF16(cc0, aH00,aH01,aH02,aH03, bh0,bh1);
            MMA_BF16(cc1, aH00,aH01,aH02,aH03, bh2,bh3);
            MMA_BF16(cc0, aH00,aH01,aH02,aH03, bl0,bl1);
            MMA_BF16(cc1, aH00,aH01,aH02,aH03, bl2,bl3);
            MMA_BF16(cc0, aL00,aL01,aL02,aL03, bh0,bh1);
            MMA_BF16(cc1, aL00,aL01,aL02,aL03, bh2,bh3);
            #pragma unroll
            for (int hh = 0; hh < 2; hh++) {
                const float* c4 = hh ? cc1 : cc0;
                int col = p*16 + hh*8 + tg*2;
                float f00 = fmaxf(c4[0] + h0p[col],   0.f);
                float f01 = fmaxf(c4[1] + h0p[col+1], 0.f);
                float f10 = fmaxf(c4[2] + h1p[col],   0.f);
                float f11 = fmaxf(c4[3] + h1p[col+1], 0.f);
                uint32_t pk0 = pack_bf2(f00, f01);
                uint32_t pk1 = pack_bf2(f10, f11);
                aH1[p][0+hh*2] = pk0;
                aH1[p][1+hh*2] = pk1;
                aL1[p][0+hh*2] = pack_bf2(f00 - __uint_as_float(pk0 << 16),
                                          f01 - __uint_as_float(pk0 & 0xffff0000u));
                aL1[p][1+hh*2] = pack_bf2(f10 - __uint_as_float(pk1 << 16),
                                          f11 - __uint_as_float(pk1 & 0xffff0000u));
            }
        }

        // ---- layer 1: K=128, fused epilogue per 16-col chunk -> w2 partials ----
        float p00=0.f,p01=0.f,p02=0.f, p10=0.f,p11=0.f,p12=0.f;
        #pragma unroll
        for (int p = 0; p < 8; p++) {
            float cc0[4] = {0.f,0.f,0.f,0.f}, cc1[4] = {0.f,0.f,0.f,0.f};
            #pragma unroll
            for (int ks = 0; ks < 8; ks++) {
                uint32_t bh0,bh1,bh2,bh3, bl0,bl1,bl2,bl3;
                LDSM_X4(bh0,bh1,bh2,bh3, aB1H + p*4352 + ks*32);
                LDSM_X4(bl0,bl1,bl2,bl3, aB1L + p*4352 + ks*32);
                MMA_BF16(cc0, aH1[ks][0],aH1[ks][1],aH1[ks][2],aH1[ks][3], bh0,bh1);
                MMA_BF16(cc1, aH1[ks][0],aH1[ks][1],aH1[ks][2],aH1[ks][3], bh2,bh3);
                MMA_BF16(cc0, aH1[ks][0],aH1[ks][1],aH1[ks][2],aH1[ks][3], bl0,bl1);
                MMA_BF16(cc1, aH1[ks][0],aH1[ks][1],aH1[ks][2],aH1[ks][3], bl2,bl3);
                MMA_BF16(cc0, aL1[ks][0],aL1[ks][1],aL1[ks][2],aL1[ks][3], bh0,bh1);
                MMA_BF16(cc1, aL1[ks][0],aL1[ks][1],aL1[ks][2],aL1[ks][3], bh2,bh3);
            }
            #pragma unroll
            for (int hh = 0; hh < 2; hh++) {
                const float* c4 = hh ? cc1 : cc0;
                int col = p*16 + hh*8 + tg*2;
                float f0 = fmaxf(c4[0] + b1s[col],   0.f);
                float f1 = fmaxf(c4[1] + b1s[col+1], 0.f);
                float f2 = fmaxf(c4[2] + b1s[col],   0.f);
                float f3 = fmaxf(c4[3] + b1s[col+1], 0.f);
                float wa0 = w2s[col*3+0],     wa1 = w2s[col*3+1],     wa2 = w2s[col*3+2];
                float wb0 = w2s[(col+1)*3+0], wb1 = w2s[(col+1)*3+1], wb2 = w2s[(col+1)*3+2];
                p00 = fmaf(f0, wa0, fmaf(f1, wb0, p00));
                p01 = fmaf(f0, wa1, fmaf(f1, wb1, p01));
                p02 = fmaf(f0, wa2, fmaf(f1, wb2, p02));
                p10 = fmaf(f2, wa0, fmaf(f3, wb0, p10));
                p11 = fmaf(f2, wa1, fmaf(f3, wb1, p11));
                p12 = fmaf(f2, wa2, fmaf(f3, wb2, p12));
            }
        }

        // ---- quad reduce + sigmoid + weighted atomic ----
        #pragma unroll
        for (int dlt = 1; dlt <= 2; dlt <<= 1) {
            p00 += __shfl_xor_sync(0xffffffffu, p00, dlt);
            p01 += __shfl_xor_sync(0xffffffffu, p01, dlt);
            p02 += __shfl_xor_sync(0xffffffffu, p02, dlt);
            p10 += __shfl_xor_sync(0xffffffffu, p10, dlt);
            p11 += __shfl_xor_sync(0xffffffffu, p11, dlt);
            p12 += __shfl_xor_sync(0xffffffffu, p12, dlt);
        }
        if (tg == 0) {
            float wg0 = g_w[s0], wg1 = g_w[s1];
            float v00 = wg0 / (1.0f + expf(-(p00 + b2r0)));
            float v01 = wg0 / (1.0f + expf(-(p01 + b2r1)));
            float v02 = wg0 / (1.0f + expf(-(p02 + b2r2)));
            float v10 = wg1 / (1.0f + expf(-(p10 + b2r0)));
            float v11 = wg1 / (1.0f + expf(-(p11 + b2r1)));
            float v12 = wg1 / (1.0f + expf(-(p12 + b2r2)));
            atomicAdd(&out[r0*3+0], v00);
            atomicAdd(&out[r0*3+1], v01);
            atomicAdd(&out[r0*3+2], v02);
            atomicAdd(&out[r1*3+0], v10);
            atomicAdd(&out[r1*3+1], v11);
            atomicAdd(&out[r1*3+2], v12);
        }

        // ---- stage next tile into alternate buffer ----
        if (hn) {
            uint32_t ab = SM_A0 + (uint32_t)(buf^1)*12288u + halfoff;
            *(uint4*)(smem + ab + srow*48)      = q0n;
            *(uint4*)(smem + ab + srow*48 + 16) = q1n;
        }
        __syncthreads();
        buf ^= 1;
    }
}

// ---------------- launcher ----------------
extern "C" void kernel_launch(void* const* d_in, const int* in_sizes, int n_in,
                              void* d_out, int out_size)
{
    const float* rays_o   = (const float*)d_in[0];
    const float* rays_d   = (const float*)d_in[1];
    const float* viewdirs = (const float*)d_in[2];
    const float* dgrid    = (const float*)d_in[3];
    const float* k0g      = (const float*)d_in[4];
    const float* w0 = (const float*)d_in[5];
    const float* b0 = (const float*)d_in[6];
    const float* w1 = (const float*)d_in[7];
    const float* b1 = (const float*)d_in[8];
    const float* w2 = (const float*)d_in[9];
    const float* b2 = (const float*)d_in[10];
    const int* stepsize = (const int*)d_in[11];
    float* out = (float*)d_out;

    cudaFuncSetAttribute(k_mlp, cudaFuncAttributeMaxDynamicSharedMemorySize, SMEM_TOTAL);

    k_sample<<<(MTOT + 255) / 256, 256>>>(rays_o, rays_d, dgrid, k0g, stepsize);
    k_scan<<<(N_RAYS * 32 + 255) / 256, 256>>>(viewdirs, out);
    k_h0v<<<(N_RAYS * 128) / 256, 256>>>(w0, b0);
    k_mlp<<<GRID_MLP, 256, SMEM_TOTAL>>>(w0, b0, w1, b1, w2, b2, out);
}